// round 11
// baseline (speedup 1.0000x reference)
#include <cuda_runtime.h>
#include <math.h>

#define NN 50000
#define EE 800000
#define RR 32
#define BB 15
#define HH 8
#define CC 16
#define WPAD 129   // padded row stride (floats) for w2 in smem: et -> distinct banks

// ---- scratch (device globals; no allocation allowed) ----
__device__ __align__(16) int   g_counts[NN * RR];              // 6.4 MB
__device__ __align__(16) float g_w1[(size_t)RR * NN * HH];     // 51.2 MB
__device__ __align__(16) float g_w2[RR * HH * CC];             // 16 KB
__device__ __align__(16) float g_norm[EE];                     // 3.2 MB
__device__ __align__(16) float g_agg1[NN * HH];                // 1.6 MB (pre-relu x)
__device__ __align__(16) float g_agg2[NN * CC];                // 3.2 MB

__device__ __forceinline__ void red_add_v4(float* addr, float a, float b,
                                           float c, float d) {
    asm volatile("red.global.add.v4.f32 [%0], {%1,%2,%3,%4};"
                 :: "l"(addr), "f"(a), "f"(b), "f"(c), "f"(d) : "memory");
}

// ---- 0. setup: zero counts/agg2, pre-bias agg1 with root1+bias1, tiny w2 ----
__global__ void k_setup(const float* __restrict__ basis2,
                        const float* __restrict__ comp2,
                        const float* __restrict__ root1,
                        const float* __restrict__ bias1) {
    int i = blockIdx.x * blockDim.x + threadIdx.x;
    int stride = gridDim.x * blockDim.x;
    if (i < RR * HH * CC) {           // w2[r,h,c] = sum_b comp2[r,b]*basis2[b,h,c]
        int r  = i / (HH * CC);
        int hc = i % (HH * CC);
        float s = 0.0f;
#pragma unroll
        for (int b = 0; b < BB; b++)
            s += comp2[r * BB + b] * basis2[b * (HH * CC) + hc];
        g_w2[i] = s;
    }
    float4 z4 = make_float4(0.f, 0.f, 0.f, 0.f);
    int4   zi = make_int4(0, 0, 0, 0);
    for (int j = i; j < NN * RR / 4; j += stride) ((int4*)g_counts)[j] = zi;
    for (int j = i; j < NN * CC / 4; j += stride) ((float4*)g_agg2)[j] = z4;
    // agg1 := root1 + bias1 (scatter1 REDs messages on top; relu applied on read)
    const float4* r4 = (const float4*)root1;
    float b0 = bias1[0], b1 = bias1[1], b2 = bias1[2], b3 = bias1[3];
    float b4v = bias1[4], b5 = bias1[5], b6 = bias1[6], b7 = bias1[7];
    for (int j = i; j < NN * HH / 4; j += stride) {
        float4 v = r4[j];
        if ((j & 1) == 0) { v.x += b0; v.y += b1; v.z += b2; v.w += b3; }
        else              { v.x += b4v; v.y += b5; v.z += b6; v.w += b7; }
        ((float4*)g_agg1)[j] = v;
    }
}

// ---- 1. FUSED: per-(tgt,rel) counts (all threads) + w1 materialize (low ids) ----
__global__ void k_cw1(const int* __restrict__ edge_index,
                      const int* __restrict__ edge_type,
                      const float* __restrict__ basis1,
                      const float* __restrict__ comp1) {
    __shared__ float sc[RR * BB];
    int p = blockIdx.x * blockDim.x + threadIdx.x;
    bool w1block = (blockIdx.x * blockDim.x) < (NN * HH / 4);
    if (w1block) {
        for (int i = threadIdx.x; i < RR * BB; i += blockDim.x) sc[i] = comp1[i];
        __syncthreads();
    }
    if (p < EE / 2) {
        int2 tgt = ((const int2*)(edge_index + EE))[p];
        int2 et  = ((const int2*)edge_type)[p];
        atomicAdd(&g_counts[tgt.x * RR + et.x], 1);
        atomicAdd(&g_counts[tgt.y * RR + et.y], 1);
    }
    if (p < NN * HH / 4) {
        const float4* b4 = (const float4*)basis1;
        float4 bv[BB];
#pragma unroll
        for (int b = 0; b < BB; b++) bv[b] = __ldg(&b4[b * (NN * HH / 4) + p]);
        float4* w4 = (float4*)g_w1;
#pragma unroll 4
        for (int r = 0; r < RR; r++) {
            float4 s = make_float4(0.f, 0.f, 0.f, 0.f);
#pragma unroll
            for (int b = 0; b < BB; b++) {
                float c = sc[r * BB + b];
                s.x += c * bv[b].x; s.y += c * bv[b].y;
                s.z += c * bv[b].z; s.w += c * bv[b].w;
            }
            w4[(size_t)r * (NN * HH / 4) + p] = s;
        }
    }
}

// ---- 2. layer-1 scatter, 2 edges/thread (saves per-edge norm) ----
__global__ void k_scatter1(const int* __restrict__ edge_index,
                           const int* __restrict__ edge_type) {
    int p = blockIdx.x * blockDim.x + threadIdx.x;
    if (p >= EE / 2) return;
    int2 src = ((const int2*)edge_index)[p];
    int2 tgt = ((const int2*)(edge_index + EE))[p];
    int2 et  = ((const int2*)edge_type)[p];
    float c0 = (float)g_counts[tgt.x * RR + et.x];
    float c1 = (float)g_counts[tgt.y * RR + et.y];
    float n0 = 1.0f / fmaxf(c0, 1.0f);
    float n1 = 1.0f / fmaxf(c1, 1.0f);
    ((float2*)g_norm)[p] = make_float2(n0, n1);
    const float4* wa = (const float4*)&g_w1[(size_t)et.x * (NN * HH) + src.x * HH];
    const float4* wb = (const float4*)&g_w1[(size_t)et.y * (NN * HH) + src.y * HH];
    float4 a0 = wa[0], a1 = wa[1];
    float4 b0 = wb[0], b1 = wb[1];
    float* d0 = &g_agg1[tgt.x * HH];
    float* d1 = &g_agg1[tgt.y * HH];
    red_add_v4(d0,     n0 * a0.x, n0 * a0.y, n0 * a0.z, n0 * a0.w);
    red_add_v4(d0 + 4, n0 * a1.x, n0 * a1.y, n0 * a1.z, n0 * a1.w);
    red_add_v4(d1,     n1 * b0.x, n1 * b0.y, n1 * b0.z, n1 * b0.w);
    red_add_v4(d1 + 4, n1 * b1.x, n1 * b1.y, n1 * b1.z, n1 * b1.w);
}

// ---- 3. layer-2 scatter: 1 edge/thread, high occupancy, relu on gather ----
__global__ void __launch_bounds__(256, 8)
k_scatter2(const int* __restrict__ edge_index,
           const int* __restrict__ edge_type) {
    __shared__ float sw[RR * WPAD];   // 32 x 129 floats = 16.5 KB
    for (int i = threadIdx.x; i < RR * HH * CC; i += blockDim.x) {
        int r  = i / (HH * CC);
        int hc = i % (HH * CC);
        sw[r * WPAD + hc] = g_w2[i];
    }
    __syncthreads();
    int e = blockIdx.x * blockDim.x + threadIdx.x;
    if (e >= EE) return;
    int src = __ldg(&edge_index[e]);
    int tgt = __ldg(&edge_index[EE + e]);
    int et  = __ldg(&edge_type[e]);
    float norm = __ldg(&g_norm[e]);
    float4 x0 = *(const float4*)&g_agg1[src * HH];
    float4 x1 = *(const float4*)&g_agg1[src * HH + 4];
    float xv[HH] = {fmaxf(x0.x,0.f), fmaxf(x0.y,0.f), fmaxf(x0.z,0.f), fmaxf(x0.w,0.f),
                    fmaxf(x1.x,0.f), fmaxf(x1.y,0.f), fmaxf(x1.z,0.f), fmaxf(x1.w,0.f)};
    const float* w = &sw[et * WPAD];
    float s[CC];
#pragma unroll
    for (int c = 0; c < CC; c++) s[c] = 0.0f;
#pragma unroll
    for (int h = 0; h < HH; h++) {
        float xh = xv[h];
#pragma unroll
        for (int c = 0; c < CC; c++) s[c] += xh * w[h * CC + c];
    }
    float* dst = &g_agg2[tgt * CC];
#pragma unroll
    for (int c = 0; c < CC; c += 4)
        red_add_v4(dst + c, norm * s[c], norm * s[c + 1],
                            norm * s[c + 2], norm * s[c + 3]);
}

// ---- 4. out = log_softmax(agg2 + relu(agg1) @ root2 + bias2) ----
__global__ void k_final(const float* __restrict__ root2,
                        const float* __restrict__ bias2,
                        float* __restrict__ out) {
    __shared__ float sr[HH * CC];
    __shared__ float sb[CC];
    for (int i = threadIdx.x; i < HH * CC; i += blockDim.x) sr[i] = root2[i];
    if (threadIdx.x < CC) sb[threadIdx.x] = bias2[threadIdx.x];
    __syncthreads();
    int n = blockIdx.x * blockDim.x + threadIdx.x;
    if (n >= NN) return;
    float4 x0 = *(const float4*)&g_agg1[n * HH];
    float4 x1 = *(const float4*)&g_agg1[n * HH + 4];
    float xv[HH] = {fmaxf(x0.x,0.f), fmaxf(x0.y,0.f), fmaxf(x0.z,0.f), fmaxf(x0.w,0.f),
                    fmaxf(x1.x,0.f), fmaxf(x1.y,0.f), fmaxf(x1.z,0.f), fmaxf(x1.w,0.f)};
    float v[CC];
    float m = -INFINITY;
#pragma unroll
    for (int c = 0; c < CC; c++) {
        float s = g_agg2[n * CC + c] + sb[c];
#pragma unroll
        for (int h = 0; h < HH; h++) s += xv[h] * sr[h * CC + c];
        v[c] = s;
        m = fmaxf(m, s);
    }
    float sum = 0.0f;
#pragma unroll
    for (int c = 0; c < CC; c++) sum += __expf(v[c] - m);
    float lse = m + __logf(sum);
#pragma unroll
    for (int c = 0; c < CC; c++) out[n * CC + c] = v[c] - lse;
}

extern "C" void kernel_launch(void* const* d_in, const int* in_sizes, int n_in,
                              void* d_out, int out_size) {
    const int*   edge_index = (const int*)d_in[0];   // (2, E)
    const int*   edge_type  = (const int*)d_in[1];   // (E,)
    const float* basis1     = (const float*)d_in[2]; // (B, N, H)
    const float* comp1      = (const float*)d_in[3]; // (R, B)
    const float* root1      = (const float*)d_in[4]; // (N, H)
    const float* bias1      = (const float*)d_in[5]; // (H,)
    const float* basis2     = (const float*)d_in[6]; // (B, H, C)
    const float* comp2      = (const float*)d_in[7]; // (R, B)
    const float* root2      = (const float*)d_in[8]; // (H, C)
    const float* bias2      = (const float*)d_in[9]; // (C,)
    float* out = (float*)d_out;

    k_setup<<<2048, 256>>>(basis2, comp2, root1, bias1);               // idx 0
    k_cw1<<<(EE / 2 + 255) / 256, 256>>>(edge_index, edge_type,
                                         basis1, comp1);               // idx 1
    k_scatter1<<<(EE / 2 + 255) / 256, 256>>>(edge_index, edge_type);  // idx 2
    k_scatter2<<<(EE + 255) / 256, 256>>>(edge_index, edge_type);      // idx 3 (profiled)
    k_final<<<(NN + 127) / 128, 128>>>(root2, bias2, out);             // idx 4
}

// round 12
// speedup vs baseline: 1.0949x; 1.0949x over previous
#include <cuda_runtime.h>
#include <cuda_fp16.h>
#include <math.h>

#define NN 50000
#define EE 800000
#define RR 32
#define BB 15
#define HH 8
#define CC 16
#define WPAD 129   // padded row stride (floats) for w2 in smem: et -> distinct banks

// ---- scratch (device globals; no allocation allowed) ----
__device__ __align__(16) int    g_counts[NN * RR];             // 6.4 MB
__device__ __align__(16) __half g_w1h[(size_t)RR * NN * HH];   // 25.6 MB (fp16 table)
__device__ __align__(16) float  g_w2[RR * HH * CC];            // 16 KB
__device__ __align__(16) float  g_norm[EE];                    // 3.2 MB
__device__ __align__(16) float  g_agg1[NN * HH];               // 1.6 MB (pre-relu x)
__device__ __align__(16) float  g_agg2[NN * CC];               // 3.2 MB

__device__ __forceinline__ void red_add_v4(float* addr, float a, float b,
                                           float c, float d) {
    asm volatile("red.global.add.v4.f32 [%0], {%1,%2,%3,%4};"
                 :: "l"(addr), "f"(a), "f"(b), "f"(c), "f"(d) : "memory");
}

// ---- 0. setup: zero counts/agg2, pre-bias agg1 with root1+bias1, tiny w2 ----
__global__ void k_setup(const float* __restrict__ basis2,
                        const float* __restrict__ comp2,
                        const float* __restrict__ root1,
                        const float* __restrict__ bias1) {
    int i = blockIdx.x * blockDim.x + threadIdx.x;
    int stride = gridDim.x * blockDim.x;
    if (i < RR * HH * CC) {           // w2[r,h,c] = sum_b comp2[r,b]*basis2[b,h,c]
        int r  = i / (HH * CC);
        int hc = i % (HH * CC);
        float s = 0.0f;
#pragma unroll
        for (int b = 0; b < BB; b++)
            s += comp2[r * BB + b] * basis2[b * (HH * CC) + hc];
        g_w2[i] = s;
    }
    float4 z4 = make_float4(0.f, 0.f, 0.f, 0.f);
    int4   zi = make_int4(0, 0, 0, 0);
    for (int j = i; j < NN * RR / 4; j += stride) ((int4*)g_counts)[j] = zi;
    for (int j = i; j < NN * CC / 4; j += stride) ((float4*)g_agg2)[j] = z4;
    const float4* r4 = (const float4*)root1;
    float b0 = bias1[0], b1 = bias1[1], b2 = bias1[2], b3 = bias1[3];
    float b4v = bias1[4], b5 = bias1[5], b6 = bias1[6], b7 = bias1[7];
    for (int j = i; j < NN * HH / 4; j += stride) {
        float4 v = r4[j];
        if ((j & 1) == 0) { v.x += b0; v.y += b1; v.z += b2; v.w += b3; }
        else              { v.x += b4v; v.y += b5; v.z += b6; v.w += b7; }
        ((float4*)g_agg1)[j] = v;
    }
}

// ---- 1. FUSED: counts (all threads) + fp16 w1 materialize (low ids) ----
__global__ void k_cw1(const int* __restrict__ edge_index,
                      const int* __restrict__ edge_type,
                      const float* __restrict__ basis1,
                      const float* __restrict__ comp1) {
    __shared__ float sc[RR * BB];
    int p = blockIdx.x * blockDim.x + threadIdx.x;
    bool w1block = (blockIdx.x * blockDim.x) < (NN * HH / 4);
    if (w1block) {
        for (int i = threadIdx.x; i < RR * BB; i += blockDim.x) sc[i] = comp1[i];
        __syncthreads();
    }
    if (p < EE / 2) {
        int2 tgt = ((const int2*)(edge_index + EE))[p];
        int2 et  = ((const int2*)edge_type)[p];
        atomicAdd(&g_counts[tgt.x * RR + et.x], 1);
        atomicAdd(&g_counts[tgt.y * RR + et.y], 1);
    }
    if (p < NN * HH / 4) {
        const float4* b4 = (const float4*)basis1;
        float4 bv[BB];
#pragma unroll
        for (int b = 0; b < BB; b++) bv[b] = __ldg(&b4[b * (NN * HH / 4) + p]);
        uint2* w2p = (uint2*)g_w1h;    // 4 halves per quad
#pragma unroll 4
        for (int r = 0; r < RR; r++) {
            float4 s = make_float4(0.f, 0.f, 0.f, 0.f);
#pragma unroll
            for (int b = 0; b < BB; b++) {
                float c = sc[r * BB + b];
                s.x += c * bv[b].x; s.y += c * bv[b].y;
                s.z += c * bv[b].z; s.w += c * bv[b].w;
            }
            __half2 h0 = __floats2half2_rn(s.x, s.y);
            __half2 h1 = __floats2half2_rn(s.z, s.w);
            uint2 packed;
            packed.x = *(unsigned*)&h0;
            packed.y = *(unsigned*)&h1;
            w2p[(size_t)r * (NN * HH / 4) + p] = packed;
        }
    }
}

// ---- 2. layer-1 scatter, 2 edges/thread; fp16 row gather (one LDG.128 each) ----
__global__ void k_scatter1(const int* __restrict__ edge_index,
                           const int* __restrict__ edge_type) {
    int p = blockIdx.x * blockDim.x + threadIdx.x;
    if (p >= EE / 2) return;
    int2 src = ((const int2*)edge_index)[p];
    int2 tgt = ((const int2*)(edge_index + EE))[p];
    int2 et  = ((const int2*)edge_type)[p];
    float c0 = (float)g_counts[tgt.x * RR + et.x];
    float c1 = (float)g_counts[tgt.y * RR + et.y];
    float n0 = 1.0f / fmaxf(c0, 1.0f);
    float n1 = 1.0f / fmaxf(c1, 1.0f);
    ((float2*)g_norm)[p] = make_float2(n0, n1);
    // one 16-byte gather per edge (8 halves)
    uint4 ra = *(const uint4*)&g_w1h[(size_t)et.x * (NN * HH) + src.x * HH];
    uint4 rb = *(const uint4*)&g_w1h[(size_t)et.y * (NN * HH) + src.y * HH];
    float2 a0 = __half22float2(*(__half2*)&ra.x);
    float2 a1 = __half22float2(*(__half2*)&ra.y);
    float2 a2 = __half22float2(*(__half2*)&ra.z);
    float2 a3 = __half22float2(*(__half2*)&ra.w);
    float2 b0 = __half22float2(*(__half2*)&rb.x);
    float2 b1 = __half22float2(*(__half2*)&rb.y);
    float2 b2 = __half22float2(*(__half2*)&rb.z);
    float2 b3 = __half22float2(*(__half2*)&rb.w);
    float* d0 = &g_agg1[tgt.x * HH];
    float* d1 = &g_agg1[tgt.y * HH];
    red_add_v4(d0,     n0 * a0.x, n0 * a0.y, n0 * a1.x, n0 * a1.y);
    red_add_v4(d0 + 4, n0 * a2.x, n0 * a2.y, n0 * a3.x, n0 * a3.y);
    red_add_v4(d1,     n1 * b0.x, n1 * b0.y, n1 * b1.x, n1 * b1.y);
    red_add_v4(d1 + 4, n1 * b2.x, n1 * b2.y, n1 * b3.x, n1 * b3.y);
}

// ---- 3. layer-2 scatter: 2 edges/thread (R10 config), relu on gather ----
__global__ void k_scatter2(const int* __restrict__ edge_index,
                           const int* __restrict__ edge_type) {
    __shared__ float sw[RR * WPAD];   // 32 x 129 floats = 16.5 KB
    for (int i = threadIdx.x; i < RR * HH * CC; i += blockDim.x) {
        int r  = i / (HH * CC);
        int hc = i % (HH * CC);
        sw[r * WPAD + hc] = g_w2[i];
    }
    __syncthreads();
    int p = blockIdx.x * blockDim.x + threadIdx.x;
    if (p >= EE / 2) return;
    int2 src = ((const int2*)edge_index)[p];
    int2 tgt = ((const int2*)(edge_index + EE))[p];
    int2 et  = ((const int2*)edge_type)[p];
    float2 nm = ((const float2*)g_norm)[p];
    float4 xa0 = *(const float4*)&g_agg1[src.x * HH];
    float4 xa1 = *(const float4*)&g_agg1[src.x * HH + 4];
    float4 xb0 = *(const float4*)&g_agg1[src.y * HH];
    float4 xb1 = *(const float4*)&g_agg1[src.y * HH + 4];
    float xva[HH] = {fmaxf(xa0.x,0.f), fmaxf(xa0.y,0.f), fmaxf(xa0.z,0.f), fmaxf(xa0.w,0.f),
                     fmaxf(xa1.x,0.f), fmaxf(xa1.y,0.f), fmaxf(xa1.z,0.f), fmaxf(xa1.w,0.f)};
    float xvb[HH] = {fmaxf(xb0.x,0.f), fmaxf(xb0.y,0.f), fmaxf(xb0.z,0.f), fmaxf(xb0.w,0.f),
                     fmaxf(xb1.x,0.f), fmaxf(xb1.y,0.f), fmaxf(xb1.z,0.f), fmaxf(xb1.w,0.f)};
    const float* wa = &sw[et.x * WPAD];
    const float* wb = &sw[et.y * WPAD];
    float sa[CC], sb[CC];
#pragma unroll
    for (int c = 0; c < CC; c++) { sa[c] = 0.0f; sb[c] = 0.0f; }
#pragma unroll
    for (int h = 0; h < HH; h++) {
        float xh0 = xva[h], xh1 = xvb[h];
#pragma unroll
        for (int c = 0; c < CC; c++) {
            sa[c] += xh0 * wa[h * CC + c];
            sb[c] += xh1 * wb[h * CC + c];
        }
    }
    float* d0 = &g_agg2[tgt.x * CC];
    float* d1 = &g_agg2[tgt.y * CC];
#pragma unroll
    for (int c = 0; c < CC; c += 4)
        red_add_v4(d0 + c, nm.x * sa[c], nm.x * sa[c + 1],
                           nm.x * sa[c + 2], nm.x * sa[c + 3]);
#pragma unroll
    for (int c = 0; c < CC; c += 4)
        red_add_v4(d1 + c, nm.y * sb[c], nm.y * sb[c + 1],
                           nm.y * sb[c + 2], nm.y * sb[c + 3]);
}

// ---- 4. out = log_softmax(agg2 + relu(agg1) @ root2 + bias2) ----
__global__ void k_final(const float* __restrict__ root2,
                        const float* __restrict__ bias2,
                        float* __restrict__ out) {
    __shared__ float sr[HH * CC];
    __shared__ float sb[CC];
    for (int i = threadIdx.x; i < HH * CC; i += blockDim.x) sr[i] = root2[i];
    if (threadIdx.x < CC) sb[threadIdx.x] = bias2[threadIdx.x];
    __syncthreads();
    int n = blockIdx.x * blockDim.x + threadIdx.x;
    if (n >= NN) return;
    float4 x0 = *(const float4*)&g_agg1[n * HH];
    float4 x1 = *(const float4*)&g_agg1[n * HH + 4];
    float xv[HH] = {fmaxf(x0.x,0.f), fmaxf(x0.y,0.f), fmaxf(x0.z,0.f), fmaxf(x0.w,0.f),
                    fmaxf(x1.x,0.f), fmaxf(x1.y,0.f), fmaxf(x1.z,0.f), fmaxf(x1.w,0.f)};
    float v[CC];
    float m = -INFINITY;
#pragma unroll
    for (int c = 0; c < CC; c++) {
        float s = g_agg2[n * CC + c] + sb[c];
#pragma unroll
        for (int h = 0; h < HH; h++) s += xv[h] * sr[h * CC + c];
        v[c] = s;
        m = fmaxf(m, s);
    }
    float sum = 0.0f;
#pragma unroll
    for (int c = 0; c < CC; c++) sum += __expf(v[c] - m);
    float lse = m + __logf(sum);
#pragma unroll
    for (int c = 0; c < CC; c++) out[n * CC + c] = v[c] - lse;
}

extern "C" void kernel_launch(void* const* d_in, const int* in_sizes, int n_in,
                              void* d_out, int out_size) {
    const int*   edge_index = (const int*)d_in[0];   // (2, E)
    const int*   edge_type  = (const int*)d_in[1];   // (E,)
    const float* basis1     = (const float*)d_in[2]; // (B, N, H)
    const float* comp1      = (const float*)d_in[3]; // (R, B)
    const float* root1      = (const float*)d_in[4]; // (N, H)
    const float* bias1      = (const float*)d_in[5]; // (H,)
    const float* basis2     = (const float*)d_in[6]; // (B, H, C)
    const float* comp2      = (const float*)d_in[7]; // (R, B)
    const float* root2      = (const float*)d_in[8]; // (H, C)
    const float* bias2      = (const float*)d_in[9]; // (C,)
    float* out = (float*)d_out;

    k_setup<<<2048, 256>>>(basis2, comp2, root1, bias1);               // idx 0
    k_cw1<<<(EE / 2 + 255) / 256, 256>>>(edge_index, edge_type,
                                         basis1, comp1);               // idx 1
    k_scatter1<<<(EE / 2 + 255) / 256, 256>>>(edge_index, edge_type);  // idx 2
    k_scatter2<<<(EE / 2 + 255) / 256, 256>>>(edge_index, edge_type);  // idx 3 (profiled)
    k_final<<<(NN + 127) / 128, 128>>>(root2, bias2, out);             // idx 4
}

// round 13
// speedup vs baseline: 1.1880x; 1.0850x over previous
#include <cuda_runtime.h>
#include <cuda_fp16.h>
#include <math.h>

#define NN 50000
#define EE 800000
#define RR 32
#define BB 15
#define HH 8
#define CC 16
#define WPADH 65   // half2 row stride for w2 smem: et -> distinct banks (65 odd)

// ---- scratch (device globals; no allocation allowed) ----
__device__ __align__(16) int    g_counts[NN * RR];             // 6.4 MB
__device__ __align__(16) __half g_w1h[(size_t)RR * NN * HH];   // 25.6 MB (fp16 table)
__device__ __align__(16) float  g_w2[RR * HH * CC];            // 16 KB
__device__ __align__(16) float  g_norm[EE];                    // 3.2 MB
__device__ __align__(16) float  g_agg1[NN * HH];               // 1.6 MB (pre-relu x)
__device__ __align__(16) float  g_agg2[NN * CC];               // 3.2 MB

__device__ __forceinline__ void red_add_v4(float* addr, float a, float b,
                                           float c, float d) {
    asm volatile("red.global.add.v4.f32 [%0], {%1,%2,%3,%4};"
                 :: "l"(addr), "f"(a), "f"(b), "f"(c), "f"(d) : "memory");
}

// ---- 0. setup: zero counts/agg2, pre-bias agg1 with root1+bias1, tiny w2 ----
__global__ void k_setup(const float* __restrict__ basis2,
                        const float* __restrict__ comp2,
                        const float* __restrict__ root1,
                        const float* __restrict__ bias1) {
    int i = blockIdx.x * blockDim.x + threadIdx.x;
    int stride = gridDim.x * blockDim.x;
    if (i < RR * HH * CC) {           // w2[r,h,c] = sum_b comp2[r,b]*basis2[b,h,c]
        int r  = i / (HH * CC);
        int hc = i % (HH * CC);
        float s = 0.0f;
#pragma unroll
        for (int b = 0; b < BB; b++)
            s += comp2[r * BB + b] * basis2[b * (HH * CC) + hc];
        g_w2[i] = s;
    }
    float4 z4 = make_float4(0.f, 0.f, 0.f, 0.f);
    int4   zi = make_int4(0, 0, 0, 0);
    for (int j = i; j < NN * RR / 4; j += stride) ((int4*)g_counts)[j] = zi;
    for (int j = i; j < NN * CC / 4; j += stride) ((float4*)g_agg2)[j] = z4;
    const float4* r4 = (const float4*)root1;
    float b0 = bias1[0], b1 = bias1[1], b2 = bias1[2], b3 = bias1[3];
    float b4v = bias1[4], b5 = bias1[5], b6 = bias1[6], b7 = bias1[7];
    for (int j = i; j < NN * HH / 4; j += stride) {
        float4 v = r4[j];
        if ((j & 1) == 0) { v.x += b0; v.y += b1; v.z += b2; v.w += b3; }
        else              { v.x += b4v; v.y += b5; v.z += b6; v.w += b7; }
        ((float4*)g_agg1)[j] = v;
    }
}

// ---- 1. FUSED: counts (all threads) + fp16 w1 materialize (low ids) ----
__global__ void k_cw1(const int* __restrict__ edge_index,
                      const int* __restrict__ edge_type,
                      const float* __restrict__ basis1,
                      const float* __restrict__ comp1) {
    __shared__ float sc[RR * BB];
    int p = blockIdx.x * blockDim.x + threadIdx.x;
    bool w1block = (blockIdx.x * blockDim.x) < (NN * HH / 4);
    if (w1block) {
        for (int i = threadIdx.x; i < RR * BB; i += blockDim.x) sc[i] = comp1[i];
        __syncthreads();
    }
    if (p < EE / 2) {
        int2 tgt = ((const int2*)(edge_index + EE))[p];
        int2 et  = ((const int2*)edge_type)[p];
        atomicAdd(&g_counts[tgt.x * RR + et.x], 1);
        atomicAdd(&g_counts[tgt.y * RR + et.y], 1);
    }
    if (p < NN * HH / 4) {
        const float4* b4 = (const float4*)basis1;
        float4 bv[BB];
#pragma unroll
        for (int b = 0; b < BB; b++) bv[b] = __ldg(&b4[b * (NN * HH / 4) + p]);
        uint2* w2p = (uint2*)g_w1h;    // 4 halves per quad
#pragma unroll 4
        for (int r = 0; r < RR; r++) {
            float4 s = make_float4(0.f, 0.f, 0.f, 0.f);
#pragma unroll
            for (int b = 0; b < BB; b++) {
                float c = sc[r * BB + b];
                s.x += c * bv[b].x; s.y += c * bv[b].y;
                s.z += c * bv[b].z; s.w += c * bv[b].w;
            }
            __half2 h0 = __floats2half2_rn(s.x, s.y);
            __half2 h1 = __floats2half2_rn(s.z, s.w);
            uint2 packed;
            packed.x = *(unsigned*)&h0;
            packed.y = *(unsigned*)&h1;
            w2p[(size_t)r * (NN * HH / 4) + p] = packed;
        }
    }
}

// ---- 2. layer-1 scatter, 2 edges/thread; fp16 row gather (one LDG.128 each) ----
__global__ void k_scatter1(const int* __restrict__ edge_index,
                           const int* __restrict__ edge_type) {
    int p = blockIdx.x * blockDim.x + threadIdx.x;
    if (p >= EE / 2) return;
    int2 src = ((const int2*)edge_index)[p];
    int2 tgt = ((const int2*)(edge_index + EE))[p];
    int2 et  = ((const int2*)edge_type)[p];
    float c0 = (float)g_counts[tgt.x * RR + et.x];
    float c1 = (float)g_counts[tgt.y * RR + et.y];
    float n0 = 1.0f / fmaxf(c0, 1.0f);
    float n1 = 1.0f / fmaxf(c1, 1.0f);
    ((float2*)g_norm)[p] = make_float2(n0, n1);
    uint4 ra = *(const uint4*)&g_w1h[(size_t)et.x * (NN * HH) + src.x * HH];
    uint4 rb = *(const uint4*)&g_w1h[(size_t)et.y * (NN * HH) + src.y * HH];
    float2 a0 = __half22float2(*(__half2*)&ra.x);
    float2 a1 = __half22float2(*(__half2*)&ra.y);
    float2 a2 = __half22float2(*(__half2*)&ra.z);
    float2 a3 = __half22float2(*(__half2*)&ra.w);
    float2 b0 = __half22float2(*(__half2*)&rb.x);
    float2 b1 = __half22float2(*(__half2*)&rb.y);
    float2 b2 = __half22float2(*(__half2*)&rb.z);
    float2 b3 = __half22float2(*(__half2*)&rb.w);
    float* d0 = &g_agg1[tgt.x * HH];
    float* d1 = &g_agg1[tgt.y * HH];
    red_add_v4(d0,     n0 * a0.x, n0 * a0.y, n0 * a1.x, n0 * a1.y);
    red_add_v4(d0 + 4, n0 * a2.x, n0 * a2.y, n0 * a3.x, n0 * a3.y);
    red_add_v4(d1,     n1 * b0.x, n1 * b0.y, n1 * b1.x, n1 * b1.y);
    red_add_v4(d1 + 4, n1 * b2.x, n1 * b2.y, n1 * b3.x, n1 * b3.y);
}

// ---- 3. layer-2 scatter: 2 edges/thread, fp16 weights in smem ----
// smem row r holds 64 half2 (h*8 + c2), stride WPADH=65 -> bank = (et + ...)%32
__global__ void k_scatter2(const int* __restrict__ edge_index,
                           const int* __restrict__ edge_type) {
    __shared__ __half2 sw[RR * WPADH];   // 32 x 65 half2 = 8.1 KB
    for (int i = threadIdx.x; i < RR * HH * CC / 2; i += blockDim.x) {
        int r  = i / (HH * CC / 2);
        int p2 = i % (HH * CC / 2);       // pair index: h*8 + c/2
        sw[r * WPADH + p2] = __floats2half2_rn(g_w2[r * HH * CC + p2 * 2],
                                               g_w2[r * HH * CC + p2 * 2 + 1]);
    }
    __syncthreads();
    int p = blockIdx.x * blockDim.x + threadIdx.x;
    if (p >= EE / 2) return;
    int2 src = ((const int2*)edge_index)[p];
    int2 tgt = ((const int2*)(edge_index + EE))[p];
    int2 et  = ((const int2*)edge_type)[p];
    float2 nm = ((const float2*)g_norm)[p];
    float4 xa0 = *(const float4*)&g_agg1[src.x * HH];
    float4 xa1 = *(const float4*)&g_agg1[src.x * HH + 4];
    float4 xb0 = *(const float4*)&g_agg1[src.y * HH];
    float4 xb1 = *(const float4*)&g_agg1[src.y * HH + 4];
    float xva[HH] = {fmaxf(xa0.x,0.f), fmaxf(xa0.y,0.f), fmaxf(xa0.z,0.f), fmaxf(xa0.w,0.f),
                     fmaxf(xa1.x,0.f), fmaxf(xa1.y,0.f), fmaxf(xa1.z,0.f), fmaxf(xa1.w,0.f)};
    float xvb[HH] = {fmaxf(xb0.x,0.f), fmaxf(xb0.y,0.f), fmaxf(xb0.z,0.f), fmaxf(xb0.w,0.f),
                     fmaxf(xb1.x,0.f), fmaxf(xb1.y,0.f), fmaxf(xb1.z,0.f), fmaxf(xb1.w,0.f)};
    const __half2* wa = &sw[et.x * WPADH];
    const __half2* wb = &sw[et.y * WPADH];
    float sa[CC], sb[CC];
#pragma unroll
    for (int c = 0; c < CC; c++) { sa[c] = 0.0f; sb[c] = 0.0f; }
#pragma unroll
    for (int h = 0; h < HH; h++) {
        float xh0 = xva[h], xh1 = xvb[h];
#pragma unroll
        for (int c2 = 0; c2 < CC / 2; c2++) {
            float2 wfa = __half22float2(wa[h * (CC / 2) + c2]);
            float2 wfb = __half22float2(wb[h * (CC / 2) + c2]);
            sa[c2 * 2]     += xh0 * wfa.x;
            sa[c2 * 2 + 1] += xh0 * wfa.y;
            sb[c2 * 2]     += xh1 * wfb.x;
            sb[c2 * 2 + 1] += xh1 * wfb.y;
        }
    }
    float* d0 = &g_agg2[tgt.x * CC];
    float* d1 = &g_agg2[tgt.y * CC];
#pragma unroll
    for (int c = 0; c < CC; c += 4)
        red_add_v4(d0 + c, nm.x * sa[c], nm.x * sa[c + 1],
                           nm.x * sa[c + 2], nm.x * sa[c + 3]);
#pragma unroll
    for (int c = 0; c < CC; c += 4)
        red_add_v4(d1 + c, nm.y * sb[c], nm.y * sb[c + 1],
                           nm.y * sb[c + 2], nm.y * sb[c + 3]);
}

// ---- 4. out = log_softmax(agg2 + relu(agg1) @ root2 + bias2) ----
__global__ void k_final(const float* __restrict__ root2,
                        const float* __restrict__ bias2,
                        float* __restrict__ out) {
    __shared__ float sr[HH * CC];
    __shared__ float sb[CC];
    for (int i = threadIdx.x; i < HH * CC; i += blockDim.x) sr[i] = root2[i];
    if (threadIdx.x < CC) sb[threadIdx.x] = bias2[threadIdx.x];
    __syncthreads();
    int n = blockIdx.x * blockDim.x + threadIdx.x;
    if (n >= NN) return;
    float4 x0 = *(const float4*)&g_agg1[n * HH];
    float4 x1 = *(const float4*)&g_agg1[n * HH + 4];
    float xv[HH] = {fmaxf(x0.x,0.f), fmaxf(x0.y,0.f), fmaxf(x0.z,0.f), fmaxf(x0.w,0.f),
                    fmaxf(x1.x,0.f), fmaxf(x1.y,0.f), fmaxf(x1.z,0.f), fmaxf(x1.w,0.f)};
    float v[CC];
    float m = -INFINITY;
#pragma unroll
    for (int c = 0; c < CC; c++) {
        float s = g_agg2[n * CC + c] + sb[c];
#pragma unroll
        for (int h = 0; h < HH; h++) s += xv[h] * sr[h * CC + c];
        v[c] = s;
        m = fmaxf(m, s);
    }
    float sum = 0.0f;
#pragma unroll
    for (int c = 0; c < CC; c++) sum += __expf(v[c] - m);
    float lse = m + __logf(sum);
#pragma unroll
    for (int c = 0; c < CC; c++) out[n * CC + c] = v[c] - lse;
}

extern "C" void kernel_launch(void* const* d_in, const int* in_sizes, int n_in,
                              void* d_out, int out_size) {
    const int*   edge_index = (const int*)d_in[0];   // (2, E)
    const int*   edge_type  = (const int*)d_in[1];   // (E,)
    const float* basis1     = (const float*)d_in[2]; // (B, N, H)
    const float* comp1      = (const float*)d_in[3]; // (R, B)
    const float* root1      = (const float*)d_in[4]; // (N, H)
    const float* bias1      = (const float*)d_in[5]; // (H,)
    const float* basis2     = (const float*)d_in[6]; // (B, H, C)
    const float* comp2      = (const float*)d_in[7]; // (R, B)
    const float* root2      = (const float*)d_in[8]; // (H, C)
    const float* bias2      = (const float*)d_in[9]; // (C,)
    float* out = (float*)d_out;

    k_setup<<<2048, 256>>>(basis2, comp2, root1, bias1);               // idx 0
    k_cw1<<<(EE / 2 + 255) / 256, 256>>>(edge_index, edge_type,
                                         basis1, comp1);               // idx 1
    k_scatter1<<<(EE / 2 + 255) / 256, 256>>>(edge_index, edge_type);  // idx 2
    k_scatter2<<<(EE / 2 + 255) / 256, 256>>>(edge_index, edge_type);  // idx 3 (profiled)
    k_final<<<(NN + 127) / 128, 128>>>(root2, bias2, out);             // idx 4
}